// round 14
// baseline (speedup 1.0000x reference)
#include <cuda_runtime.h>
#include <cstdint>

#define NPTS   8192
#define NFEAT  256
#define SPLITS 64
#define CHUNK  (NPTS / SPLITS)      // 128 refs = 32 quads -> 2KB smem
#define NN_BLOCKS   (NPTS / 256 * SPLITS)   // 2048
#define COPY_BLOCKS 128

// Per-split packed argmin partials: (ordered_d2_bits << 32) | ref_index.
__device__ unsigned long long g_part[SPLITS * NPTS];
__device__ int g_inds[NPTS];

__device__ __forceinline__ unsigned int float_order(float f) {
    unsigned int u = __float_as_uint(f);
    return (u & 0x80000000u) ? ~u : (u | 0x80000000u);
}

// ---- packed f32x2 helpers (FFMA2 is PTX-only; ptxas won't auto-fuse) ----
__device__ __forceinline__ uint64_t bcast2(float f) {
    uint64_t r; asm("mov.b64 %0, {%1, %1};" : "=l"(r) : "f"(f)); return r;
}
__device__ __forceinline__ uint64_t fma2(uint64_t a, uint64_t b, uint64_t c) {
    uint64_t d; asm("fma.rn.f32x2 %0, %1, %2, %3;" : "=l"(d) : "l"(a), "l"(b), "l"(c));
    return d;
}
__device__ __forceinline__ void unpack2(uint64_t v, float& lo, float& hi) {
    asm("mov.b64 {%0, %1}, %2;" : "=f"(lo), "=f"(hi) : "l"(v));
}
__device__ __forceinline__ void lds_v2u64(uint32_t addr, uint64_t& a, uint64_t& b) {
    asm volatile("ld.shared.v2.u64 {%0, %1}, [%2];" : "=l"(a), "=l"(b) : "r"(addr));
}

// grid(NN_BLOCKS + COPY_BLOCKS), block(128). No occupancy cap (caps spill).
// Blocks [0, NN_BLOCKS): argmin. qtile = b & 31, split = b >> 5.
//   Each thread owns queries q0, q0+128. Deferral grain = QUAD (4 refs):
//   per quad per query: tree-min(4) -> 1 cmp -> gm-min -> idx select.
// Blocks [NN_BLOCKS, +COPY_BLOCKS): stream-copy emb2 -> out upper half.
__global__ void __launch_bounds__(128) nn_argmin_kernel(
    const float* __restrict__ t1,   // refs  [3, NPTS]
    const float* __restrict__ t2,   // query [3, NPTS]
    const float* __restrict__ emb2,
    float* __restrict__ out)
{
    const int tid = threadIdx.x;

    if (blockIdx.x >= NN_BLOCKS) {
        const int c = blockIdx.x - NN_BLOCKS;
        const float4* src = (const float4*)emb2;
        float4* dst = (float4*)(out + (size_t)NFEAT * NPTS);
        #pragma unroll
        for (int i = 0; i < 32; ++i) {
            const int o = c * 4096 + i * 128 + tid;
            dst[o] = src[o];
        }
        return;
    }

    __shared__ float4 refs[CHUNK];          // 128 float4 = 2KB
    const int split = blockIdx.x >> 5;
    const int qtile = blockIdx.x & 31;
    const int base  = split * CHUNK;

    // Prologue: threads 0..63 each pack one ref pair:
    // pair i -> {x0,x1,y0,y1},{z0,z1,w0,w1}.
    if (tid < CHUNK / 2) {
        const int r2 = tid * 2;
        float2 x2 = *(const float2*)(t1 + base + r2);
        float2 y2 = *(const float2*)(t1 + NPTS + base + r2);
        float2 z2 = *(const float2*)(t1 + 2 * NPTS + base + r2);
        float w0 = fmaf(x2.x, x2.x, fmaf(y2.x, y2.x, z2.x * z2.x));
        float w1 = fmaf(x2.y, x2.y, fmaf(y2.y, y2.y, z2.y * z2.y));
        refs[2 * tid]     = make_float4(x2.x, x2.y, y2.x, y2.y);
        refs[2 * tid + 1] = make_float4(z2.x, z2.y, w0, w1);
    }
    __syncthreads();

    const int q0 = qtile * 256 + tid;
    const uint64_t aa0 = bcast2(-2.0f * t2[q0]);
    const uint64_t bb0 = bcast2(-2.0f * t2[NPTS + q0]);
    const uint64_t cc0 = bcast2(-2.0f * t2[2 * NPTS + q0]);
    const uint64_t aa1 = bcast2(-2.0f * t2[q0 + 128]);
    const uint64_t bb1 = bcast2(-2.0f * t2[NPTS + q0 + 128]);
    const uint64_t cc1 = bcast2(-2.0f * t2[2 * NPTS + q0 + 128]);

    // One running min + winning-QUAD index per query.
    float gm0 = 3.4e38f, gm1 = 3.4e38f;
    int   bi0 = 0,       bi1 = 0;

    const uint32_t sbase = (uint32_t)__cvta_generic_to_shared(refs);

    // v = fma(a,x, fma(b,y, fma(c,z, w))) — identical chain to all passing
    // kernels: every argmin decision bit-identical. Strict '<' on the quad
    // min: bi records the FIRST quad attaining the final minimum.
    #pragma unroll 4
    for (int i = 0; i < CHUNK / 4; ++i) {   // 32 quads
        uint64_t xA, yA, zA, wA, xB, yB, zB, wB;
        lds_v2u64(sbase + i * 64,      xA, yA);
        lds_v2u64(sbase + i * 64 + 16, zA, wA);
        lds_v2u64(sbase + i * 64 + 32, xB, yB);
        lds_v2u64(sbase + i * 64 + 48, zB, wB);

        uint64_t v0A = fma2(aa0, xA, fma2(bb0, yA, fma2(cc0, zA, wA)));
        uint64_t v0B = fma2(aa0, xB, fma2(bb0, yB, fma2(cc0, zB, wB)));
        uint64_t v1A = fma2(aa1, xA, fma2(bb1, yA, fma2(cc1, zA, wA)));
        uint64_t v1B = fma2(aa1, xB, fma2(bb1, yB, fma2(cc1, zB, wB)));

        float a0e, a0o, b0e, b0o, a1e, a1o, b1e, b1o;
        unpack2(v0A, a0e, a0o);
        unpack2(v0B, b0e, b0o);
        unpack2(v1A, a1e, a1o);
        unpack2(v1B, b1e, b1o);

        float m0 = fminf(fminf(a0e, a0o), fminf(b0e, b0o));
        float m1 = fminf(fminf(a1e, a1o), fminf(b1e, b1o));
        bool p0 = m0 < gm0;
        bool p1 = m1 < gm1;
        gm0 = fminf(gm0, m0);
        gm1 = fminf(gm1, m1);
        bi0 = p0 ? i : bi0;
        bi1 = p1 ? i : bi1;
    }

    // Epilogue: recompute the winning quad (bit-exact; gm is a bit-copy of
    // one of its 4 halves) and take the FIRST half equal to gm -> lowest
    // index on intra-quad ties = jnp.argmin first-occurrence semantics.
    int idx0, idx1;
    {
        uint64_t xA, yA, zA, wA, xB, yB, zB, wB;
        lds_v2u64(sbase + bi0 * 64,      xA, yA);
        lds_v2u64(sbase + bi0 * 64 + 16, zA, wA);
        lds_v2u64(sbase + bi0 * 64 + 32, xB, yB);
        lds_v2u64(sbase + bi0 * 64 + 48, zB, wB);
        uint64_t vA = fma2(aa0, xA, fma2(bb0, yA, fma2(cc0, zA, wA)));
        uint64_t vB = fma2(aa0, xB, fma2(bb0, yB, fma2(cc0, zB, wB)));
        float ae, ao, be, bo;
        unpack2(vA, ae, ao);
        unpack2(vB, be, bo);
        int off = (ae == gm0) ? 0 : ((ao == gm0) ? 1 : ((be == gm0) ? 2 : 3));
        idx0 = base + 4 * bi0 + off;
    }
    {
        uint64_t xA, yA, zA, wA, xB, yB, zB, wB;
        lds_v2u64(sbase + bi1 * 64,      xA, yA);
        lds_v2u64(sbase + bi1 * 64 + 16, zA, wA);
        lds_v2u64(sbase + bi1 * 64 + 32, xB, yB);
        lds_v2u64(sbase + bi1 * 64 + 48, zB, wB);
        uint64_t vA = fma2(aa1, xA, fma2(bb1, yA, fma2(cc1, zA, wA)));
        uint64_t vB = fma2(aa1, xB, fma2(bb1, yB, fma2(cc1, zB, wB)));
        float ae, ao, be, bo;
        unpack2(vA, ae, ao);
        unpack2(vB, be, bo);
        int off = (ae == gm1) ? 0 : ((ao == gm1) ? 1 : ((be == gm1) ? 2 : 3));
        idx1 = base + 4 * bi1 + off;
    }

    g_part[split * NPTS + q0] =
        ((unsigned long long)float_order(gm0) << 32) | (unsigned int)idx0;
    g_part[split * NPTS + q0 + 128] =
        ((unsigned long long)float_order(gm1) << 32) | (unsigned int)idx1;
}

// combine: 8 lanes per query, 8 splits per lane, shfl-reduced.
// grid(256), block(256).
__global__ void __launch_bounds__(256) combine_kernel() {
    const int tid  = threadIdx.x;
    const int q    = (blockIdx.x * 256 + tid) >> 3;   // 8 threads per query
    const int lane = tid & 7;

    unsigned long long m = 0xFFFFFFFFFFFFFFFFull;
    #pragma unroll
    for (int s = 0; s < 8; ++s) {
        unsigned long long v = g_part[(lane + s * 8) * NPTS + q];
        m = (v < m) ? v : m;
    }
    #pragma unroll
    for (int d = 4; d > 0; d >>= 1) {
        unsigned long long o = __shfl_xor_sync(0xFFFFFFFFu, m, d);
        m = (o < m) ? o : m;
    }
    if (lane == 0)
        g_inds[q] = (int)(unsigned int)(m & 0xFFFFFFFFull);
}

// gather: 4 blocks per emb1 row. grid(4*NFEAT=1024), block(256).
// Each block loads the full row into smem (L2 dedups the 4x reads) and
// gathers a 2048-query quarter via LDS; float4 coalesced stores.
__global__ void __launch_bounds__(256) gather_kernel(
    const float* __restrict__ emb1,
    float* __restrict__ out)
{
    const int tid     = threadIdx.x;
    const int row     = blockIdx.x >> 2;
    const int quarter = blockIdx.x & 3;

    __shared__ float srow[NPTS];
    const float4* rowsrc = (const float4*)(emb1 + (size_t)row * NPTS);
    float4* srow4 = (float4*)srow;
    #pragma unroll
    for (int i = 0; i < NPTS / 4 / 256; ++i)        // 8 float4 per thread
        srow4[i * 256 + tid] = rowsrc[i * 256 + tid];
    __syncthreads();

    const int joff = quarter * (NPTS / 4);          // 2048-query quarter
    float* dst = out + (size_t)row * NPTS + joff;
    const int* inds = g_inds + joff;
    #pragma unroll
    for (int k = 0; k < 2; ++k) {
        const int j = tid * 4 + k * 1024;
        int4 iv = *(const int4*)(inds + j);
        float4 v = make_float4(srow[iv.x], srow[iv.y], srow[iv.z], srow[iv.w]);
        *(float4*)(dst + j) = v;
    }
}

extern "C" void kernel_launch(void* const* d_in, const int* in_sizes, int n_in,
                              void* d_out, int out_size) {
    const float* emb1 = (const float*)d_in[0];
    const float* emb2 = (const float*)d_in[1];
    const float* t1   = (const float*)d_in[2];
    const float* t2   = (const float*)d_in[3];
    float* out = (float*)d_out;

    nn_argmin_kernel<<<NN_BLOCKS + COPY_BLOCKS, 128>>>(t1, t2, emb2, out);
    combine_kernel<<<256, 256>>>();
    gather_kernel<<<4 * NFEAT, 256>>>(emb1, out);
}

// round 15
// speedup vs baseline: 1.0012x; 1.0012x over previous
#include <cuda_runtime.h>
#include <cstdint>

#define NPTS   8192
#define NFEAT  256
#define SPLITS 64
#define CHUNK  (NPTS / SPLITS)      // 128 refs = 64 pairs -> 2KB smem
#define NN_BLOCKS   (NPTS / 256 * SPLITS)   // 2048
#define COPY_BLOCKS 128

// Per-split packed argmin partials: (ordered_d2_bits << 32) | ref_index.
__device__ unsigned long long g_part[SPLITS * NPTS];
__device__ int g_inds[NPTS];

__device__ __forceinline__ unsigned int float_order(float f) {
    unsigned int u = __float_as_uint(f);
    return (u & 0x80000000u) ? ~u : (u | 0x80000000u);
}

// ---- packed f32x2 helpers (FFMA2 is PTX-only; ptxas won't auto-fuse) ----
__device__ __forceinline__ uint64_t bcast2(float f) {
    uint64_t r; asm("mov.b64 %0, {%1, %1};" : "=l"(r) : "f"(f)); return r;
}
__device__ __forceinline__ uint64_t fma2(uint64_t a, uint64_t b, uint64_t c) {
    uint64_t d; asm("fma.rn.f32x2 %0, %1, %2, %3;" : "=l"(d) : "l"(a), "l"(b), "l"(c));
    return d;
}
__device__ __forceinline__ void unpack2(uint64_t v, float& lo, float& hi) {
    asm("mov.b64 {%0, %1}, %2;" : "=f"(lo), "=f"(hi) : "l"(v));
}

// grid(NN_BLOCKS + COPY_BLOCKS), block(128). No occupancy cap (caps spill).
// Blocks [0, NN_BLOCKS): argmin. qtile = b & 31, split = b >> 5.
//   Plain C++ smem loads (NO asm volatile): ptxas is free to software-
//   pipeline LDS across the unrolled iterations — the volatile fence was
//   pinning issue at ~60% in rounds 5-14.
// Blocks [NN_BLOCKS, +COPY_BLOCKS): stream-copy emb2 -> out upper half.
__global__ void __launch_bounds__(128) nn_argmin_kernel(
    const float* __restrict__ t1,   // refs  [3, NPTS]
    const float* __restrict__ t2,   // query [3, NPTS]
    const float* __restrict__ emb2,
    float* __restrict__ out)
{
    const int tid = threadIdx.x;

    if (blockIdx.x >= NN_BLOCKS) {
        const int c = blockIdx.x - NN_BLOCKS;
        const float4* src = (const float4*)emb2;
        float4* dst = (float4*)(out + (size_t)NFEAT * NPTS);
        #pragma unroll
        for (int i = 0; i < 32; ++i) {
            const int o = c * 4096 + i * 128 + tid;
            dst[o] = src[o];
        }
        return;
    }

    __shared__ float4 refs[CHUNK];          // 128 float4 = 2KB
    const int split = blockIdx.x >> 5;
    const int qtile = blockIdx.x & 31;
    const int base  = split * CHUNK;

    // Prologue: threads 0..63 each pack one ref pair:
    // pair i -> {x0,x1,y0,y1},{z0,z1,w0,w1}.
    if (tid < CHUNK / 2) {
        const int r2 = tid * 2;
        float2 x2 = *(const float2*)(t1 + base + r2);
        float2 y2 = *(const float2*)(t1 + NPTS + base + r2);
        float2 z2 = *(const float2*)(t1 + 2 * NPTS + base + r2);
        float w0 = fmaf(x2.x, x2.x, fmaf(y2.x, y2.x, z2.x * z2.x));
        float w1 = fmaf(x2.y, x2.y, fmaf(y2.y, y2.y, z2.y * z2.y));
        refs[2 * tid]     = make_float4(x2.x, x2.y, y2.x, y2.y);
        refs[2 * tid + 1] = make_float4(z2.x, z2.y, w0, w1);
    }
    __syncthreads();

    const int q0 = qtile * 256 + tid;
    const uint64_t aa0 = bcast2(-2.0f * t2[q0]);
    const uint64_t bb0 = bcast2(-2.0f * t2[NPTS + q0]);
    const uint64_t cc0 = bcast2(-2.0f * t2[2 * NPTS + q0]);
    const uint64_t aa1 = bcast2(-2.0f * t2[q0 + 128]);
    const uint64_t bb1 = bcast2(-2.0f * t2[NPTS + q0 + 128]);
    const uint64_t cc1 = bcast2(-2.0f * t2[2 * NPTS + q0 + 128]);

    // One running min + winning-pair index per query; parity deferred.
    float gm0 = 3.4e38f, gm1 = 3.4e38f;
    int   bi0 = 0,       bi1 = 0;

    const ulonglong2* refs2 = (const ulonglong2*)refs;   // {x01,y01},{z01,w01}

    // v = fma(a,x, fma(b,y, fma(c,z, w))) — identical chain to all passing
    // kernels: every argmin decision bit-identical. Strict '<' on
    // m = min(ve,vo): bi records the FIRST pair attaining the final min.
    #pragma unroll 4
    for (int i = 0; i < CHUNK / 2; ++i) {
        const ulonglong2 pA = refs2[2 * i];       // x01, y01
        const ulonglong2 pB = refs2[2 * i + 1];   // z01, w01

        uint64_t v0p = fma2(aa0, pA.x, fma2(bb0, pA.y, fma2(cc0, pB.x, pB.y)));
        uint64_t v1p = fma2(aa1, pA.x, fma2(bb1, pA.y, fma2(cc1, pB.x, pB.y)));

        float v0e, v0o, v1e, v1o;
        unpack2(v0p, v0e, v0o);
        unpack2(v1p, v1e, v1o);

        float m0 = fminf(v0e, v0o);
        float m1 = fminf(v1e, v1o);
        bool p0 = m0 < gm0;
        bool p1 = m1 < gm1;
        gm0 = fminf(gm0, m0);
        gm1 = fminf(gm1, m1);
        bi0 = p0 ? i : bi0;
        bi1 = p1 ? i : bi1;
    }

    // Epilogue: resolve parity by recomputing the winning pair (bit-exact;
    // gm is a bit-copy of one half). ve == gm -> even (lower index) wins,
    // preserving first-occurrence on intra-pair ties.
    int idx0, idx1;
    {
        const ulonglong2 pA = refs2[2 * bi0];
        const ulonglong2 pB = refs2[2 * bi0 + 1];
        uint64_t vp = fma2(aa0, pA.x, fma2(bb0, pA.y, fma2(cc0, pB.x, pB.y)));
        float ve, vo; unpack2(vp, ve, vo);
        idx0 = base + 2 * bi0 + ((ve == gm0) ? 0 : 1);
    }
    {
        const ulonglong2 pA = refs2[2 * bi1];
        const ulonglong2 pB = refs2[2 * bi1 + 1];
        uint64_t vp = fma2(aa1, pA.x, fma2(bb1, pA.y, fma2(cc1, pB.x, pB.y)));
        float ve, vo; unpack2(vp, ve, vo);
        idx1 = base + 2 * bi1 + ((ve == gm1) ? 0 : 1);
    }

    g_part[split * NPTS + q0] =
        ((unsigned long long)float_order(gm0) << 32) | (unsigned int)idx0;
    g_part[split * NPTS + q0 + 128] =
        ((unsigned long long)float_order(gm1) << 32) | (unsigned int)idx1;
}

// combine: 8 lanes per query, 8 splits per lane, shfl-reduced.
// grid(256), block(256).
__global__ void __launch_bounds__(256) combine_kernel() {
    const int tid  = threadIdx.x;
    const int q    = (blockIdx.x * 256 + tid) >> 3;   // 8 threads per query
    const int lane = tid & 7;

    unsigned long long m = 0xFFFFFFFFFFFFFFFFull;
    #pragma unroll
    for (int s = 0; s < 8; ++s) {
        unsigned long long v = g_part[(lane + s * 8) * NPTS + q];
        m = (v < m) ? v : m;
    }
    #pragma unroll
    for (int d = 4; d > 0; d >>= 1) {
        unsigned long long o = __shfl_xor_sync(0xFFFFFFFFu, m, d);
        m = (o < m) ? o : m;
    }
    if (lane == 0)
        g_inds[q] = (int)(unsigned int)(m & 0xFFFFFFFFull);
}

// gather: 4 blocks per emb1 row. grid(4*NFEAT=1024), block(256).
// Each block loads the full row into smem (L2 dedups the 4x reads) and
// gathers a 2048-query quarter via LDS; float4 coalesced stores.
__global__ void __launch_bounds__(256) gather_kernel(
    const float* __restrict__ emb1,
    float* __restrict__ out)
{
    const int tid     = threadIdx.x;
    const int row     = blockIdx.x >> 2;
    const int quarter = blockIdx.x & 3;

    __shared__ float srow[NPTS];
    const float4* rowsrc = (const float4*)(emb1 + (size_t)row * NPTS);
    float4* srow4 = (float4*)srow;
    #pragma unroll
    for (int i = 0; i < NPTS / 4 / 256; ++i)        // 8 float4 per thread
        srow4[i * 256 + tid] = rowsrc[i * 256 + tid];
    __syncthreads();

    const int joff = quarter * (NPTS / 4);          // 2048-query quarter
    float* dst = out + (size_t)row * NPTS + joff;
    const int* inds = g_inds + joff;
    #pragma unroll
    for (int k = 0; k < 2; ++k) {
        const int j = tid * 4 + k * 1024;
        int4 iv = *(const int4*)(inds + j);
        float4 v = make_float4(srow[iv.x], srow[iv.y], srow[iv.z], srow[iv.w]);
        *(float4*)(dst + j) = v;
    }
}

extern "C" void kernel_launch(void* const* d_in, const int* in_sizes, int n_in,
                              void* d_out, int out_size) {
    const float* emb1 = (const float*)d_in[0];
    const float* emb2 = (const float*)d_in[1];
    const float* t1   = (const float*)d_in[2];
    const float* t2   = (const float*)d_in[3];
    float* out = (float*)d_out;

    nn_argmin_kernel<<<NN_BLOCKS + COPY_BLOCKS, 128>>>(t1, t2, emb2, out);
    combine_kernel<<<256, 256>>>();
    gather_kernel<<<4 * NFEAT, 256>>>(emb1, out);
}